// round 1
// baseline (speedup 1.0000x reference)
#include <cuda_runtime.h>
#include <math.h>

// Problem constants
#define MB 8192      // batch
#define NB 4096      // 4*H
#define KB 2048      // D + H
#define HDIM 1024
#define DDIM 1024

// 128 MB scratch for the gate pre-activations (allowed: __device__ global)
__device__ float g_gates[(size_t)MB * NB];

// ---------------------------------------------------------------------------
// GEMM: gates[m, n] = sum_k A[m,k] * W[n,k] + b[n]
//   A[m,k] = x[m,k]            (k < 1024)
//          = h_prev[m,k-1024]  (k >= 1024)
//   W[n,k] = Wx[n,k]           (k < 1024)
//          = Wh[n,k-1024]      (k >= 1024)
// Tile: 128x128x16, 256 threads, 8x8 accumulators per thread.
// ---------------------------------------------------------------------------
__global__ __launch_bounds__(256, 2)
void lstm_gemm_gates(const float* __restrict__ x,
                     const float* __restrict__ h_prev,
                     const float* __restrict__ Wx,
                     const float* __restrict__ Wh,
                     const float* __restrict__ bias)
{
    __shared__ float As[16][128];
    __shared__ float Ws[16][128];

    const int tid = threadIdx.x;
    const int tx = tid & 15;          // 0..15 -> n direction
    const int ty = tid >> 4;          // 0..15 -> m direction

    const int block_m = blockIdx.y * 128;
    const int block_n = blockIdx.x * 128;

    float acc[8][8];
#pragma unroll
    for (int i = 0; i < 8; i++)
#pragma unroll
        for (int j = 0; j < 8; j++)
            acc[i][j] = 0.0f;

    // Global-load mapping: 128 rows x 16 cols per tile = 512 float4 loads,
    // 256 threads -> 2 float4 per thread.
    // id = tid + it*256 ; r = id/4 ; c4 = (id%4)*4
    for (int kt = 0; kt < KB; kt += 16) {
#pragma unroll
        for (int it = 0; it < 2; it++) {
            int id = tid + it * 256;
            int r = id >> 2;
            int c4 = (id & 3) << 2;
            int kk = kt + c4;

            // ---- A tile ----
            {
                int m = block_m + r;
                const float* src = (kk < DDIM)
                    ? (x + (size_t)m * DDIM + kk)
                    : (h_prev + (size_t)m * HDIM + (kk - DDIM));
                float4 v = *reinterpret_cast<const float4*>(src);
                As[c4 + 0][r] = v.x;
                As[c4 + 1][r] = v.y;
                As[c4 + 2][r] = v.z;
                As[c4 + 3][r] = v.w;
            }
            // ---- W tile ----
            {
                int n = block_n + r;
                const float* src = (kk < DDIM)
                    ? (Wx + (size_t)n * DDIM + kk)
                    : (Wh + (size_t)n * HDIM + (kk - DDIM));
                float4 v = *reinterpret_cast<const float4*>(src);
                Ws[c4 + 0][r] = v.x;
                Ws[c4 + 1][r] = v.y;
                Ws[c4 + 2][r] = v.z;
                Ws[c4 + 3][r] = v.w;
            }
        }
        __syncthreads();

#pragma unroll
        for (int k = 0; k < 16; k++) {
            float a[8], w[8];
#pragma unroll
            for (int i = 0; i < 8; i += 4) {
                float4 va = *reinterpret_cast<const float4*>(&As[k][ty * 8 + i]);
                a[i + 0] = va.x; a[i + 1] = va.y; a[i + 2] = va.z; a[i + 3] = va.w;
                float4 vw = *reinterpret_cast<const float4*>(&Ws[k][tx * 8 + i]);
                w[i + 0] = vw.x; w[i + 1] = vw.y; w[i + 2] = vw.z; w[i + 3] = vw.w;
            }
#pragma unroll
            for (int i = 0; i < 8; i++)
#pragma unroll
                for (int j = 0; j < 8; j++)
                    acc[i][j] = fmaf(a[i], w[j], acc[i][j]);
        }
        __syncthreads();
    }

    // Epilogue: add bias, store to scratch.
#pragma unroll
    for (int i = 0; i < 8; i++) {
        int m = block_m + ty * 8 + i;
        float* dst = g_gates + (size_t)m * NB + block_n + tx * 8;
#pragma unroll
        for (int j = 0; j < 8; j += 4) {
            int n = block_n + tx * 8 + j;
            float4 v;
            v.x = acc[i][j + 0] + bias[n + 0];
            v.y = acc[i][j + 1] + bias[n + 1];
            v.z = acc[i][j + 2] + bias[n + 2];
            v.w = acc[i][j + 3] + bias[n + 3];
            *reinterpret_cast<float4*>(dst + j) = v;
        }
    }
}

// ---------------------------------------------------------------------------
// Elementwise LSTM gate math.
//   i = gates[m, h], f = gates[m, H+h], o = gates[m, 2H+h], g = gates[m, 3H+h]
//   c_t = sigmoid(f)*c_prev + sigmoid(i)*tanh(g)
//   h_t = sigmoid(o)*tanh(c_t)
// Output layout: out[0 .. MB*H) = h_t ; out[MB*H .. 2*MB*H) = c_t
// ---------------------------------------------------------------------------
__device__ __forceinline__ float sigmoidf_(float v) {
    return 1.0f / (1.0f + expf(-v));
}

__global__ __launch_bounds__(256)
void lstm_elementwise(const float* __restrict__ c_prev,
                      float* __restrict__ out)
{
    // float4 over the [MB, HDIM] plane
    size_t idx4 = (size_t)blockIdx.x * blockDim.x + threadIdx.x;  // float4 index
    size_t total4 = (size_t)MB * HDIM / 4;
    if (idx4 >= total4) return;

    size_t elem = idx4 * 4;
    size_t m = elem / HDIM;
    size_t h = elem % HDIM;

    const float* grow = g_gates + m * NB;
    float4 gi = *reinterpret_cast<const float4*>(grow + h);
    float4 gf = *reinterpret_cast<const float4*>(grow + HDIM + h);
    float4 go = *reinterpret_cast<const float4*>(grow + 2 * HDIM + h);
    float4 gg = *reinterpret_cast<const float4*>(grow + 3 * HDIM + h);
    float4 cp = *reinterpret_cast<const float4*>(c_prev + elem);

    float4 ct, ht;
    {
        float c = sigmoidf_(gf.x) * cp.x + sigmoidf_(gi.x) * tanhf(gg.x);
        ct.x = c; ht.x = sigmoidf_(go.x) * tanhf(c);
    }
    {
        float c = sigmoidf_(gf.y) * cp.y + sigmoidf_(gi.y) * tanhf(gg.y);
        ct.y = c; ht.y = sigmoidf_(go.y) * tanhf(c);
    }
    {
        float c = sigmoidf_(gf.z) * cp.z + sigmoidf_(gi.z) * tanhf(gg.z);
        ct.z = c; ht.z = sigmoidf_(go.z) * tanhf(c);
    }
    {
        float c = sigmoidf_(gf.w) * cp.w + sigmoidf_(gi.w) * tanhf(gg.w);
        ct.w = c; ht.w = sigmoidf_(go.w) * tanhf(c);
    }

    *reinterpret_cast<float4*>(out + elem) = ht;
    *reinterpret_cast<float4*>(out + (size_t)MB * HDIM + elem) = ct;
}

extern "C" void kernel_launch(void* const* d_in, const int* in_sizes, int n_in,
                              void* d_out, int out_size)
{
    const float* x      = (const float*)d_in[0];  // [8192, 1024]
    const float* h_prev = (const float*)d_in[1];  // [8192, 1024]
    const float* c_prev = (const float*)d_in[2];  // [8192, 1024]
    const float* Wx     = (const float*)d_in[3];  // [4096, 1024]
    const float* Wh     = (const float*)d_in[4];  // [4096, 1024]
    const float* bias   = (const float*)d_in[5];  // [4096]
    float* out = (float*)d_out;                   // [2 * 8192 * 1024]

    dim3 grid(NB / 128, MB / 128);   // (32, 64)
    lstm_gemm_gates<<<grid, 256>>>(x, h_prev, Wx, Wh, bias);

    size_t total4 = (size_t)MB * HDIM / 4;
    int blocks = (int)((total4 + 255) / 256);
    lstm_elementwise<<<blocks, 256>>>(c_prev, out);
}

// round 3
// speedup vs baseline: 4.1305x; 4.1305x over previous
#include <cuda_runtime.h>
#include <cstdint>
#include <math.h>

#define MB 8192
#define NB 4096
#define KB 2048
#define HDIM 1024

#define BM 128
#define BN 128
#define BK 32
#define STAGES 3
#define NSLABS (KB / BK)          // 64

#define TILE_BYTES (BM * BK * 4)  // 16384 each for A and B
#define STAGE_BYTES (2 * TILE_BYTES)
#define SMEM_TOTAL (STAGES * STAGE_BYTES)   // 98304

// gate pre-activation scratch (128 MB)
__device__ float g_gates[(size_t)MB * NB];

// ---------------------------------------------------------------------------
// PTX helpers (sm_80-era ISA only: cp.async / ldmatrix / mma.sync)
// ---------------------------------------------------------------------------
__device__ __forceinline__ uint32_t smem_u32(const void* p) {
    uint32_t a;
    asm("{ .reg .u64 t; cvta.to.shared.u64 t, %1; cvt.u32.u64 %0, t; }"
        : "=r"(a) : "l"(p));
    return a;
}

#define CP_ASYNC16(dst, src) \
    asm volatile("cp.async.cg.shared.global [%0], [%1], 16;" \
                 :: "r"(dst), "l"(src) : "memory")
#define CP_COMMIT() asm volatile("cp.async.commit_group;" ::: "memory")
#define CP_WAIT(n)  asm volatile("cp.async.wait_group %0;" :: "n"(n) : "memory")

#define LDM_X4(r0, r1, r2, r3, addr) \
    asm volatile("ldmatrix.sync.aligned.m8n8.x4.shared.b16 {%0,%1,%2,%3}, [%4];" \
                 : "=r"(r0), "=r"(r1), "=r"(r2), "=r"(r3) : "r"(addr))

#define TO_TF32(u) \
    asm volatile("cvt.rna.tf32.f32 %0, %1;" : "=r"(u) : "f"(__uint_as_float(u)))

#define MMA_TF32(d, a, b0, b1) \
    asm volatile("mma.sync.aligned.m16n8k8.row.col.f32.tf32.tf32.f32 " \
                 "{%0,%1,%2,%3}, {%4,%5,%6,%7}, {%8,%9}, {%0,%1,%2,%3};" \
                 : "+f"((d)[0]), "+f"((d)[1]), "+f"((d)[2]), "+f"((d)[3]) \
                 : "r"((a)[0]), "r"((a)[1]), "r"((a)[2]), "r"((a)[3]), \
                   "r"(b0), "r"(b1))

// SW128-style XOR swizzle on (row, 16B-column) within a [128 x 128B] tile
__device__ __forceinline__ uint32_t swz(int row, int c16) {
    return (uint32_t)(row * 128 + ((c16 ^ (row & 7)) << 4));
}

// ---------------------------------------------------------------------------
// GEMM: gates[m,n] = sum_k A[m,k] * W[n,k] + b[n]
//   A = [x | h_prev], W = [Wx | Wh], both K-major with row stride 1024.
// CTA 128x128x32, 3-stage cp.async pipeline, 8 warps (2 m x 4 n), warp tile
// 64x32, mma.sync.m16n8k8 tf32 with rna rounding.
// ---------------------------------------------------------------------------
__global__ __launch_bounds__(256, 2)
void lstm_gemm_mma(const float* __restrict__ x,
                   const float* __restrict__ h_prev,
                   const float* __restrict__ Wx,
                   const float* __restrict__ Wh,
                   const float* __restrict__ bias)
{
    extern __shared__ char smem[];
    const uint32_t tiles = smem_u32(smem);

    const int tid = threadIdx.x;
    const int wid = tid >> 5;
    const int lid = tid & 31;
    const int warp_m = wid & 1;        // 2 warps along M (64 rows each)
    const int warp_n = wid >> 1;       // 4 warps along N (32 cols each)
    const int block_m = blockIdx.y * BM;
    const int block_n = blockIdx.x * BN;

    // cp.async gmem->smem mapping: 1024 x 16B chunks per tile, 4 per thread
    const int ld_r   = tid >> 3;       // 0..31 base row (stride 32 over 4 iters)
    const int ld_c16 = tid & 7;        // 16B column

    float acc[2][4][2][4];             // wrong dims? -> [4 m-frag][4 n-frag][4]
    // NOTE: use flat layout [4][4][4] below instead
    (void)acc;

    float c[4][4][4];
#pragma unroll
    for (int i = 0; i < 4; i++)
#pragma unroll
        for (int j = 0; j < 4; j++)
#pragma unroll
            for (int q = 0; q < 4; q++)
                c[i][j][q] = 0.0f;

    // ---- stage loader ----
    auto load_stage = [&](int stg, int slab) {
        const int kk = slab * BK;
        const float* Asrc = (kk < HDIM) ? (x + kk) : (h_prev + (kk - HDIM));
        const float* Bsrc = (kk < HDIM) ? (Wx + kk) : (Wh + (kk - HDIM));
        const uint32_t ab = tiles + stg * STAGE_BYTES;
        const uint32_t bb = ab + TILE_BYTES;
#pragma unroll
        for (int t = 0; t < 4; t++) {
            const int r = ld_r + t * 32;
            const uint32_t off = swz(r, ld_c16);
            CP_ASYNC16(ab + off, Asrc + (size_t)(block_m + r) * 1024 + ld_c16 * 4);
            CP_ASYNC16(bb + off, Bsrc + (size_t)(block_n + r) * 1024 + ld_c16 * 4);
        }
    };

    // prologue: prefetch STAGES-1 stages
#pragma unroll
    for (int s = 0; s < STAGES - 1; s++) {
        load_stage(s, s);
        CP_COMMIT();
    }

    // ldmatrix per-lane row/col decomposition
    const int a_row_in = (lid & 7) + ((lid >> 3) & 1) * 8;   // within m16 tile
    const int a_hi     = (lid >> 4) & 1;                     // c16 +0/+1
    const int b_row_in = (lid & 7) + ((lid >> 4) & 1) * 8;   // within n16 pair
    const int b_hi     = (lid >> 3) & 1;

    for (int slab = 0; slab < NSLABS; slab++) {
        CP_WAIT(STAGES - 2);
        __syncthreads();

        const int stg = slab % STAGES;
        const uint32_t Abase = tiles + stg * STAGE_BYTES;
        const uint32_t Bbase = Abase + TILE_BYTES;

#pragma unroll
        for (int ks = 0; ks < 4; ks++) {     // 4 x k8 per BK=32
            uint32_t a[4][4];
#pragma unroll
            for (int mi = 0; mi < 4; mi++) {
                const int row = warp_m * 64 + mi * 16 + a_row_in;
                LDM_X4(a[mi][0], a[mi][1], a[mi][2], a[mi][3],
                       Abase + swz(row, ks * 2 + a_hi));
            }
            uint32_t b[2][4];
#pragma unroll
            for (int j = 0; j < 2; j++) {
                const int row = warp_n * 32 + j * 16 + b_row_in;
                LDM_X4(b[j][0], b[j][1], b[j][2], b[j][3],
                       Bbase + swz(row, ks * 2 + b_hi));
            }
            // rna-round everything to tf32 (unbiased; truncation bias ~1e-3)
#pragma unroll
            for (int mi = 0; mi < 4; mi++) {
                TO_TF32(a[mi][0]); TO_TF32(a[mi][1]);
                TO_TF32(a[mi][2]); TO_TF32(a[mi][3]);
            }
#pragma unroll
            for (int j = 0; j < 2; j++) {
                TO_TF32(b[j][0]); TO_TF32(b[j][1]);
                TO_TF32(b[j][2]); TO_TF32(b[j][3]);
            }
#pragma unroll
            for (int mi = 0; mi < 4; mi++)
#pragma unroll
                for (int ni = 0; ni < 4; ni++)
                    MMA_TF32(c[mi][ni], a[mi],
                             b[ni >> 1][(ni & 1) * 2],
                             b[ni >> 1][(ni & 1) * 2 + 1]);
        }

        __syncthreads();
        const int next = slab + (STAGES - 1);
        if (next < NSLABS) load_stage(next % STAGES, next);
        CP_COMMIT();
    }

    // ---- epilogue: bias add + store to g_gates ----
    const int g = lid >> 2;
    const int q = lid & 3;
#pragma unroll
    for (int ni = 0; ni < 4; ni++) {
        const int col = block_n + warp_n * 32 + ni * 8 + q * 2;
        const float bx = __ldg(bias + col);
        const float by = __ldg(bias + col + 1);
#pragma unroll
        for (int mi = 0; mi < 4; mi++) {
            const int row = block_m + warp_m * 64 + mi * 16 + g;
            float2 v0 = make_float2(c[mi][ni][0] + bx, c[mi][ni][1] + by);
            float2 v1 = make_float2(c[mi][ni][2] + bx, c[mi][ni][3] + by);
            *reinterpret_cast<float2*>(g_gates + (size_t)row * NB + col) = v0;
            *reinterpret_cast<float2*>(g_gates + (size_t)(row + 8) * NB + col) = v1;
        }
    }
}

// ---------------------------------------------------------------------------
// Elementwise LSTM gate math (74% HBM already)
// ---------------------------------------------------------------------------
__device__ __forceinline__ float sigmoidf_(float v) {
    return 1.0f / (1.0f + expf(-v));
}

__global__ __launch_bounds__(256)
void lstm_elementwise(const float* __restrict__ c_prev,
                      float* __restrict__ out)
{
    size_t idx4 = (size_t)blockIdx.x * blockDim.x + threadIdx.x;
    size_t total4 = (size_t)MB * HDIM / 4;
    if (idx4 >= total4) return;

    size_t elem = idx4 * 4;
    size_t m = elem / HDIM;
    size_t h = elem % HDIM;

    const float* grow = g_gates + m * NB;
    float4 gi = *reinterpret_cast<const float4*>(grow + h);
    float4 gf = *reinterpret_cast<const float4*>(grow + HDIM + h);
    float4 go = *reinterpret_cast<const float4*>(grow + 2 * HDIM + h);
    float4 gg = *reinterpret_cast<const float4*>(grow + 3 * HDIM + h);
    float4 cp = *reinterpret_cast<const float4*>(c_prev + elem);

    float4 ct, ht;
    { float v = sigmoidf_(gf.x) * cp.x + sigmoidf_(gi.x) * tanhf(gg.x);
      ct.x = v; ht.x = sigmoidf_(go.x) * tanhf(v); }
    { float v = sigmoidf_(gf.y) * cp.y + sigmoidf_(gi.y) * tanhf(gg.y);
      ct.y = v; ht.y = sigmoidf_(go.y) * tanhf(v); }
    { float v = sigmoidf_(gf.z) * cp.z + sigmoidf_(gi.z) * tanhf(gg.z);
      ct.z = v; ht.z = sigmoidf_(go.z) * tanhf(v); }
    { float v = sigmoidf_(gf.w) * cp.w + sigmoidf_(gi.w) * tanhf(gg.w);
      ct.w = v; ht.w = sigmoidf_(go.w) * tanhf(v); }

    *reinterpret_cast<float4*>(out + elem) = ht;
    *reinterpret_cast<float4*>(out + (size_t)MB * HDIM + elem) = ct;
}

extern "C" void kernel_launch(void* const* d_in, const int* in_sizes, int n_in,
                              void* d_out, int out_size)
{
    const float* x      = (const float*)d_in[0];
    const float* h_prev = (const float*)d_in[1];
    const float* c_prev = (const float*)d_in[2];
    const float* Wx     = (const float*)d_in[3];
    const float* Wh     = (const float*)d_in[4];
    const float* bias   = (const float*)d_in[5];
    float* out = (float*)d_out;

    cudaFuncSetAttribute(lstm_gemm_mma,
                         cudaFuncAttributeMaxDynamicSharedMemorySize, SMEM_TOTAL);

    dim3 grid(NB / BN, MB / BM);   // (32, 64)
    lstm_gemm_mma<<<grid, 256, SMEM_TOTAL>>>(x, h_prev, Wx, Wh, bias);

    size_t total4 = (size_t)MB * HDIM / 4;
    int blocks = (int)((total4 + 255) / 256);
    lstm_elementwise<<<blocks, 256>>>(c_prev, out);
}

// round 4
// speedup vs baseline: 4.3989x; 1.0650x over previous
#include <cuda_runtime.h>
#include <cstdint>
#include <math.h>

#define MB 8192
#define NB 4096
#define KB 2048
#define HDIM 1024

#define BM 128
#define BN 256
#define BK 32
#define STAGES 3
#define NSLABS (KB / BK)            // 64

#define A_TILE_BYTES (BM * BK * 4)  // 16384
#define B_TILE_BYTES (BN * BK * 4)  // 32768
#define STAGE_BYTES (A_TILE_BYTES + B_TILE_BYTES)
#define SMEM_TOTAL (STAGES * STAGE_BYTES)   // 147456

// Scratch: tf32-rounded packed operands + gate pre-activations
__device__ float g_A[(size_t)MB * KB];      // 64 MB  [x | h_prev]
__device__ float g_W[(size_t)NB * KB];      // 32 MB  [Wx | Wh]
__device__ float g_gates[(size_t)MB * NB];  // 128 MB

// ---------------------------------------------------------------------------
// PTX helpers
// ---------------------------------------------------------------------------
__device__ __forceinline__ uint32_t smem_u32(const void* p) {
    uint32_t a;
    asm("{ .reg .u64 t; cvta.to.shared.u64 t, %1; cvt.u32.u64 %0, t; }"
        : "=r"(a) : "l"(p));
    return a;
}

#define CP_ASYNC16(dst, src) \
    asm volatile("cp.async.cg.shared.global [%0], [%1], 16;" \
                 :: "r"(dst), "l"(src) : "memory")
#define CP_COMMIT() asm volatile("cp.async.commit_group;" ::: "memory")
#define CP_WAIT(n)  asm volatile("cp.async.wait_group %0;" :: "n"(n) : "memory")

#define LDM_X4(r0, r1, r2, r3, addr) \
    asm volatile("ldmatrix.sync.aligned.m8n8.x4.shared.b16 {%0,%1,%2,%3}, [%4];" \
                 : "=r"(r0), "=r"(r1), "=r"(r2), "=r"(r3) : "r"(addr))

#define MMA_TF32(d, a, b0, b1) \
    asm volatile("mma.sync.aligned.m16n8k8.row.col.f32.tf32.tf32.f32 " \
                 "{%0,%1,%2,%3}, {%4,%5,%6,%7}, {%8,%9}, {%0,%1,%2,%3};" \
                 : "+f"((d)[0]), "+f"((d)[1]), "+f"((d)[2]), "+f"((d)[3]) \
                 : "r"((a)[0]), "r"((a)[1]), "r"((a)[2]), "r"((a)[3]), \
                   "r"(b0), "r"(b1))

// XOR swizzle on (row, 16B-col) within a [rows x 128B] tile
__device__ __forceinline__ uint32_t swz(int row, int c16) {
    return (uint32_t)(row * 128 + ((c16 ^ (row & 7)) << 4));
}

// ---------------------------------------------------------------------------
// Pre-pass: pack [x|h_prev] -> g_A, [Wx|Wh] -> g_W with rna tf32 rounding.
// Rounding once here (instead of per-read in the GEMM) removes 25M cvt ops
// from the compute loop; rna keeps the rounding unbiased (rel_err ~2e-4).
// ---------------------------------------------------------------------------
#define A4TOT ((size_t)MB * KB / 4)   // 4194304
#define W4TOT ((size_t)NB * KB / 4)   // 2097152

__global__ __launch_bounds__(256)
void pack_tf32(const float* __restrict__ x, const float* __restrict__ h,
               const float* __restrict__ Wx, const float* __restrict__ Wh)
{
    size_t idx = (size_t)blockIdx.x * blockDim.x + threadIdx.x;
    if (idx >= A4TOT + W4TOT) return;

    const float* src;
    float* dst;
    if (idx < A4TOT) {
        size_t row = idx >> 9;            // /512 (2048/4)
        int col = (int)(idx & 511) << 2;
        src = (col < HDIM) ? (x + row * HDIM + col)
                           : (h + row * HDIM + col - HDIM);
        dst = g_A + (row << 11) + col;
    } else {
        size_t w = idx - A4TOT;
        size_t row = w >> 9;
        int col = (int)(w & 511) << 2;
        src = (col < HDIM) ? (Wx + row * HDIM + col)
                           : (Wh + row * HDIM + col - HDIM);
        dst = g_W + (row << 11) + col;
    }
    float4 v = *reinterpret_cast<const float4*>(src);
    uint32_t t0, t1, t2, t3;
    asm volatile("cvt.rna.tf32.f32 %0, %1;" : "=r"(t0) : "f"(v.x));
    asm volatile("cvt.rna.tf32.f32 %0, %1;" : "=r"(t1) : "f"(v.y));
    asm volatile("cvt.rna.tf32.f32 %0, %1;" : "=r"(t2) : "f"(v.z));
    asm volatile("cvt.rna.tf32.f32 %0, %1;" : "=r"(t3) : "f"(v.w));
    float4 o;
    o.x = __uint_as_float(t0); o.y = __uint_as_float(t1);
    o.z = __uint_as_float(t2); o.w = __uint_as_float(t3);
    *reinterpret_cast<float4*>(dst) = o;
}

// ---------------------------------------------------------------------------
// GEMM: gates[m,n] = sum_k g_A[m,k] * g_W[n,k] + b[n]
// CTA 128x256x32, 3-stage cp.async, 512 threads (16 warps, 4m x 4n),
// warp tile 32x64, mma.sync.m16n8k8 tf32 (inputs pre-rounded).
// ---------------------------------------------------------------------------
__global__ __launch_bounds__(512, 1)
void lstm_gemm_mma(const float* __restrict__ bias)
{
    extern __shared__ char smem[];
    const uint32_t tiles = smem_u32(smem);

    const int tid = threadIdx.x;
    const int wid = tid >> 5;
    const int lid = tid & 31;
    const int warp_m = wid & 3;        // 4 warps along M (32 rows each)
    const int warp_n = wid >> 2;       // 4 warps along N (64 cols each)
    const int block_m = blockIdx.y * BM;
    const int block_n = blockIdx.x * BN;

    float c[2][8][4];
#pragma unroll
    for (int i = 0; i < 2; i++)
#pragma unroll
        for (int j = 0; j < 8; j++)
#pragma unroll
            for (int q = 0; q < 4; q++)
                c[i][j][q] = 0.0f;

    // cp.async mapping: A = 1024 chunks (2/thread), B = 2048 chunks (4/thread)
    const int ld_r   = tid >> 3;       // 0..63
    const int ld_c16 = tid & 7;

    auto load_stage = [&](int stg, int slab) {
        const int kk = slab * BK;
        const float* Asrc = g_A + kk;
        const float* Bsrc = g_W + kk;
        const uint32_t ab = tiles + stg * STAGE_BYTES;
        const uint32_t bb = ab + A_TILE_BYTES;
#pragma unroll
        for (int t = 0; t < 2; t++) {
            const int r = ld_r + t * 64;
            CP_ASYNC16(ab + swz(r, ld_c16),
                       Asrc + (size_t)(block_m + r) * KB + ld_c16 * 4);
        }
#pragma unroll
        for (int t = 0; t < 4; t++) {
            const int r = ld_r + t * 64;
            CP_ASYNC16(bb + swz(r, ld_c16),
                       Bsrc + (size_t)(block_n + r) * KB + ld_c16 * 4);
        }
    };

#pragma unroll
    for (int s = 0; s < STAGES - 1; s++) {
        load_stage(s, s);
        CP_COMMIT();
    }

    // ldmatrix per-lane decomposition (validated in R3)
    const int a_row_in = (lid & 7) + ((lid >> 3) & 1) * 8;
    const int a_hi     = (lid >> 4) & 1;
    const int b_row_in = (lid & 7) + ((lid >> 4) & 1) * 8;
    const int b_hi     = (lid >> 3) & 1;

    for (int slab = 0; slab < NSLABS; slab++) {
        CP_WAIT(STAGES - 2);
        __syncthreads();

        const int stg = slab % STAGES;
        const uint32_t Abase = tiles + stg * STAGE_BYTES;
        const uint32_t Bbase = Abase + A_TILE_BYTES;

#pragma unroll
        for (int ks = 0; ks < 4; ks++) {
            uint32_t a[2][4];
#pragma unroll
            for (int mi = 0; mi < 2; mi++) {
                const int row = warp_m * 32 + mi * 16 + a_row_in;
                LDM_X4(a[mi][0], a[mi][1], a[mi][2], a[mi][3],
                       Abase + swz(row, ks * 2 + a_hi));
            }
            uint32_t b[4][4];
#pragma unroll
            for (int j = 0; j < 4; j++) {
                const int row = warp_n * 64 + j * 16 + b_row_in;
                LDM_X4(b[j][0], b[j][1], b[j][2], b[j][3],
                       Bbase + swz(row, ks * 2 + b_hi));
            }
#pragma unroll
            for (int mi = 0; mi < 2; mi++)
#pragma unroll
                for (int ni = 0; ni < 8; ni++)
                    MMA_TF32(c[mi][ni], a[mi],
                             b[ni >> 1][(ni & 1) * 2],
                             b[ni >> 1][(ni & 1) * 2 + 1]);
        }

        __syncthreads();
        const int next = slab + (STAGES - 1);
        if (next < NSLABS) load_stage(next % STAGES, next);
        CP_COMMIT();
    }

    // ---- epilogue: bias add + store to g_gates ----
    const int g = lid >> 2;
    const int q = lid & 3;
#pragma unroll
    for (int ni = 0; ni < 8; ni++) {
        const int col = block_n + warp_n * 64 + ni * 8 + q * 2;
        const float bx = __ldg(bias + col);
        const float by = __ldg(bias + col + 1);
#pragma unroll
        for (int mi = 0; mi < 2; mi++) {
            const int row = block_m + warp_m * 32 + mi * 16 + g;
            float2 v0 = make_float2(c[mi][ni][0] + bx, c[mi][ni][1] + by);
            float2 v1 = make_float2(c[mi][ni][2] + bx, c[mi][ni][3] + by);
            *reinterpret_cast<float2*>(g_gates + (size_t)row * NB + col) = v0;
            *reinterpret_cast<float2*>(g_gates + (size_t)(row + 8) * NB + col) = v1;
        }
    }
}

// ---------------------------------------------------------------------------
// Elementwise LSTM gate math (72-74% of HBM already)
// ---------------------------------------------------------------------------
__device__ __forceinline__ float sigmoidf_(float v) {
    return 1.0f / (1.0f + expf(-v));
}

__global__ __launch_bounds__(256)
void lstm_elementwise(const float* __restrict__ c_prev,
                      float* __restrict__ out)
{
    size_t idx4 = (size_t)blockIdx.x * blockDim.x + threadIdx.x;
    size_t total4 = (size_t)MB * HDIM / 4;
    if (idx4 >= total4) return;

    size_t elem = idx4 * 4;
    size_t m = elem / HDIM;
    size_t h = elem % HDIM;

    const float* grow = g_gates + m * NB;
    float4 gi = *reinterpret_cast<const float4*>(grow + h);
    float4 gf = *reinterpret_cast<const float4*>(grow + HDIM + h);
    float4 go = *reinterpret_cast<const float4*>(grow + 2 * HDIM + h);
    float4 gg = *reinterpret_cast<const float4*>(grow + 3 * HDIM + h);
    float4 cp = *reinterpret_cast<const float4*>(c_prev + elem);

    float4 ct, ht;
    { float v = sigmoidf_(gf.x) * cp.x + sigmoidf_(gi.x) * tanhf(gg.x);
      ct.x = v; ht.x = sigmoidf_(go.x) * tanhf(v); }
    { float v = sigmoidf_(gf.y) * cp.y + sigmoidf_(gi.y) * tanhf(gg.y);
      ct.y = v; ht.y = sigmoidf_(go.y) * tanhf(v); }
    { float v = sigmoidf_(gf.z) * cp.z + sigmoidf_(gi.z) * tanhf(gg.z);
      ct.z = v; ht.z = sigmoidf_(go.z) * tanhf(v); }
    { float v = sigmoidf_(gf.w) * cp.w + sigmoidf_(gi.w) * tanhf(gg.w);
      ct.w = v; ht.w = sigmoidf_(go.w) * tanhf(v); }

    *reinterpret_cast<float4*>(out + elem) = ht;
    *reinterpret_cast<float4*>(out + (size_t)MB * HDIM + elem) = ct;
}

extern "C" void kernel_launch(void* const* d_in, const int* in_sizes, int n_in,
                              void* d_out, int out_size)
{
    const float* x      = (const float*)d_in[0];
    const float* h_prev = (const float*)d_in[1];
    const float* c_prev = (const float*)d_in[2];
    const float* Wx     = (const float*)d_in[3];
    const float* Wh     = (const float*)d_in[4];
    const float* bias   = (const float*)d_in[5];
    float* out = (float*)d_out;

    size_t packtot = A4TOT + W4TOT;
    pack_tf32<<<(int)((packtot + 255) / 256), 256>>>(x, h_prev, Wx, Wh);

    cudaFuncSetAttribute(lstm_gemm_mma,
                         cudaFuncAttributeMaxDynamicSharedMemorySize, SMEM_TOTAL);
    dim3 grid(NB / BN, MB / BM);   // (16, 64)
    lstm_gemm_mma<<<grid, 512, SMEM_TOTAL>>>(bias);

    size_t total4 = (size_t)MB * HDIM / 4;
    int blocks = (int)((total4 + 255) / 256);
    lstm_elementwise<<<blocks, 256>>>(c_prev, out);
}